// round 16
// baseline (speedup 1.0000x reference)
#include <cuda_runtime.h>
#include <cuda_bf16.h>
#include <math.h>

#define N_MAX 50000
#define E_MAX 800000
#define R_REP 8          // BN stat replica bins (kills R9's single-bin contention)

// RNN chunking: CH_S-step chunk after CH_W-step warm-up from h=0.
#define CH_S 64
#define CH_W 32

// ---------------- scratch (device globals; referenced directly in kernels) ----
__device__ float g_bufA[N_MAX * 100];          // xw (no bias) for gather
__device__ float g_bufB[N_MAX * 100];          // aggregated output
__device__ float g_dinv[N_MAX];
__device__ int   g_degi[N_MAX];                // incoming-edge histogram
__device__ int   g_rowptr[N_MAX];              // CSR: reserved base, then bumped to end
__device__ int   g_total;                      // reservation counter
__device__ int   g_colidx[E_MAX];              // CSR: src of each incoming edge
__device__ float g_pre [(N_MAX + 1) * 50];     // RNN pre-activations (+pad row)
__device__ float g_ys  [N_MAX * 50];
__device__ float g_z1  [N_MAX * 50];
__device__ float g_z2  [N_MAX * 30];
__device__ float g_sum [4][R_REP][128];        // replicated raw column sums
__device__ float g_sq  [4][R_REP][128];        // replicated raw sum-of-squares

// buffer selectors
#define XS_EXT  0
#define XS_BUFB 1
#define XS_YS   2
#define XS_Z1   3
#define OS_PRE  1
#define OS_Z1   2
#define OS_Z2   3

template<int SEL>
__device__ __forceinline__ const float* xbuf(const float* ext) {
    if (SEL == XS_BUFB) return g_bufB;
    if (SEL == XS_YS)   return g_ys;
    if (SEL == XS_Z1)   return g_z1;
    return ext;
}
template<int SEL>
__device__ __forceinline__ float* obuf() {
    if (SEL == OS_PRE)  return g_pre;
    if (SEL == OS_Z1)   return g_z1;
    return g_z2;
}

// sum the replica bins for one column
__device__ __forceinline__ void stat_read(int slot, int c, float& sm, float& sq) {
    float a = 0.f, b = 0.f;
    #pragma unroll
    for (int r = 0; r < R_REP; r++) { a += g_sum[slot][r][c]; b += g_sq[slot][r][c]; }
    sm = a; sq = b;
}

// ---------------- CSR build -----------------------------------------------------
__global__ void k_zero(int n) {
    int i = blockIdx.x * blockDim.x + threadIdx.x;
    if (i < n) g_degi[i] = 0;
    if (i == 0) g_total = 0;
    if (i < 4 * R_REP * 128) {
        ((float*)g_sum)[i] = 0.f;
        ((float*)g_sq)[i]  = 0.f;
    }
}

__global__ void k_hist(const int* __restrict__ edge, int e) {
    int i = blockIdx.x * blockDim.x + threadIdx.x;
    if (i < e) atomicAdd(&g_degi[edge[e + i]], 1);
}

__global__ void k_rowptr(int n) {
    int i = blockIdx.x * blockDim.x + threadIdx.x;
    if (i < n) {
        int d = g_degi[i];
        g_dinv[i] = rsqrtf((float)d + 1.0f);        // +1 self loop
        g_rowptr[i] = atomicAdd(&g_total, d);
    }
}

__global__ void k_fill(const int* __restrict__ edge, int e) {
    int i = blockIdx.x * blockDim.x + threadIdx.x;
    if (i < e) {
        int d = edge[e + i];
        int pos = atomicAdd(&g_rowptr[d], 1);       // rowptr -> segment END
        g_colidx[pos] = edge[i];
    }
}

// ---------------- gather + fused BN stats (replicated bins) --------------------
// warp per destination node; lanes 0..24 hold one float4 column group.
template<int SLOT>
__global__ void k_gather(const float* __restrict__ bias, int n) {
    __shared__ float ssum[100], ssq[100];
    for (int c = threadIdx.x; c < 100; c += blockDim.x) { ssum[c] = 0.f; ssq[c] = 0.f; }
    __syncthreads();

    int warp = (blockIdx.x * blockDim.x + threadIdx.x) >> 5;
    int lane = threadIdx.x & 31;
    bool act = (warp < n) && (lane < 25);
    float4 acc = make_float4(0.f, 0.f, 0.f, 0.f);

    if (warp < n) {
        int p1 = g_rowptr[warp];            // post-fill: segment end
        int p0 = p1 - g_degi[warp];         // segment base
        float dd = g_dinv[warp];
        if (act) {
            float4 v  = ((const float4*)&g_bufA[warp * 100])[lane];
            float4 bv = ((const float4*)bias)[lane];
            float d2 = dd * dd;
            acc = make_float4(bv.x + v.x * d2, bv.y + v.y * d2,
                              bv.z + v.z * d2, bv.w + v.w * d2);
        }
        int i = p0;
        for (; i + 4 <= p1; i += 4) {                // unroll x4 for MLP
            int s0 = g_colidx[i + 0], s1 = g_colidx[i + 1];
            int s2 = g_colidx[i + 2], s3 = g_colidx[i + 3];
            float n0 = g_dinv[s0] * dd, n1 = g_dinv[s1] * dd;
            float n2 = g_dinv[s2] * dd, n3 = g_dinv[s3] * dd;
            if (act) {
                float4 v0 = ((const float4*)&g_bufA[s0 * 100])[lane];
                float4 v1 = ((const float4*)&g_bufA[s1 * 100])[lane];
                float4 v2 = ((const float4*)&g_bufA[s2 * 100])[lane];
                float4 v3 = ((const float4*)&g_bufA[s3 * 100])[lane];
                acc.x += v0.x * n0; acc.y += v0.y * n0; acc.z += v0.z * n0; acc.w += v0.w * n0;
                acc.x += v1.x * n1; acc.y += v1.y * n1; acc.z += v1.z * n1; acc.w += v1.w * n1;
                acc.x += v2.x * n2; acc.y += v2.y * n2; acc.z += v2.z * n2; acc.w += v2.w * n2;
                acc.x += v3.x * n3; acc.y += v3.y * n3; acc.z += v3.z * n3; acc.w += v3.w * n3;
            }
        }
        for (; i < p1; i++) {
            int s = g_colidx[i];
            float nm = g_dinv[s] * dd;
            if (act) {
                float4 v = ((const float4*)&g_bufA[s * 100])[lane];
                acc.x += v.x * nm; acc.y += v.y * nm; acc.z += v.z * nm; acc.w += v.w * nm;
            }
        }
        if (act) {
            ((float4*)&g_bufB[warp * 100])[lane] = acc;
            int c = lane * 4;
            atomicAdd(&ssum[c + 0], acc.x); atomicAdd(&ssq[c + 0], acc.x * acc.x);
            atomicAdd(&ssum[c + 1], acc.y); atomicAdd(&ssq[c + 1], acc.y * acc.y);
            atomicAdd(&ssum[c + 2], acc.z); atomicAdd(&ssq[c + 2], acc.z * acc.z);
            atomicAdd(&ssum[c + 3], acc.w); atomicAdd(&ssq[c + 3], acc.w * acc.w);
        }
    }
    __syncthreads();
    int rb = blockIdx.x & (R_REP - 1);
    for (int c = threadIdx.x; c < 100; c += blockDim.x) {
        atomicAdd(&g_sum[SLOT][rb][c], ssum[c]);
        atomicAdd(&g_sq [SLOT][rb][c], ssq[c]);
    }
}

// ---------------- conv GEMM (IN=OUT=100): 4x4 register microtile ---------------
// 20-row tile, 125 active threads. BNS>=0: BN (+ReLU) on load (replica-summed).
template<int XSEL, int BNS, bool BRELU>
__global__ void k_gemm_conv(const float* __restrict__ Xext, const float* __restrict__ W,
                            const float* __restrict__ gam, const float* __restrict__ bet,
                            int M, float invM) {
    const float* __restrict__ X = xbuf<XSEL>(Xext);
    __shared__ __align__(16) float xs[100][28];
    __shared__ float scs[100], shs[100];

    if (BNS >= 0) {
        for (int c = threadIdx.x; c < 100; c += blockDim.x) {
            float sm, sq;
            stat_read(BNS, c, sm, sq);
            float m = sm * invM;
            float v = sq * invM - m * m;
            float s = rsqrtf(v + 1e-5f) * gam[c];
            scs[c] = s;
            shs[c] = bet[c] - m * s;
        }
        __syncthreads();
    }

    int r0 = blockIdx.x * 20;
    for (int idx = threadIdx.x; idx < 20 * 100; idx += blockDim.x) {
        int r = idx / 100, k = idx % 100;
        int gr = r0 + r;
        float xv = (gr < M) ? X[gr * 100 + k] : 0.f;
        if (BNS >= 0) {
            xv = scs[k] * xv + shs[k];
            if (BRELU) xv = fmaxf(xv, 0.f);
        }
        xs[k][r] = xv;
    }
    __syncthreads();

    int tid = threadIdx.x;
    if (tid >= 125) return;
    int cg = tid % 25;
    int rg = tid / 25;
    float acc[4][4];
    #pragma unroll
    for (int i = 0; i < 4; i++)
        #pragma unroll
        for (int jj = 0; jj < 4; jj++) acc[i][jj] = 0.f;

    #pragma unroll 2
    for (int k = 0; k < 100; k++) {
        float4 xv = *(const float4*)&xs[k][rg * 4];
        float4 wv = *(const float4*)&W[k * 100 + cg * 4];
        acc[0][0] += xv.x * wv.x; acc[0][1] += xv.x * wv.y;
        acc[0][2] += xv.x * wv.z; acc[0][3] += xv.x * wv.w;
        acc[1][0] += xv.y * wv.x; acc[1][1] += xv.y * wv.y;
        acc[1][2] += xv.y * wv.z; acc[1][3] += xv.y * wv.w;
        acc[2][0] += xv.z * wv.x; acc[2][1] += xv.z * wv.y;
        acc[2][2] += xv.z * wv.z; acc[2][3] += xv.z * wv.w;
        acc[3][0] += xv.w * wv.x; acc[3][1] += xv.w * wv.y;
        acc[3][2] += xv.w * wv.z; acc[3][3] += xv.w * wv.w;
    }

    #pragma unroll
    for (int i = 0; i < 4; i++) {
        int gr = r0 + rg * 4 + i;
        if (gr < M)
            ((float4*)&g_bufA[gr * 100])[cg] =
                make_float4(acc[i][0], acc[i][1], acc[i][2], acc[i][3]);
    }
}

// ---------------- microtiled small GEMM + optional fused output stats -----------
// ROWS=32, 4x4 microtile, W staged transposed in smem. STATS>=0: column stats
// of outputs -> replica bins (smem reduce, one global atomic/col/block).
template<int IN, int OUT, int XSEL, int OSEL, int BNS, bool BRELU, int STATS>
__global__ void k_gemm_mt(const float* __restrict__ Xext, const float* __restrict__ W,
                          const float* __restrict__ bs1, const float* __restrict__ bs2,
                          const float* __restrict__ gam, const float* __restrict__ bet,
                          int M, float invM) {
    const int ROWS = 32;
    const int CG   = (OUT + 3) / 4;
    const int OUTP = CG * 4;
    const int NT   = CG * 8;                 // compute threads (8 row-groups)
    const float* __restrict__ X = xbuf<XSEL>(Xext);
    float* __restrict__ out = obuf<OSEL>();

    __shared__ __align__(16) float xs[IN][ROWS + 4];
    __shared__ __align__(16) float Ws[IN][OUTP + 4];
    __shared__ float scs[IN], shs[IN];
    __shared__ float ssum[OUTP], ssq[OUTP];

    if (STATS >= 0) {
        for (int c = threadIdx.x; c < OUTP; c += blockDim.x) { ssum[c] = 0.f; ssq[c] = 0.f; }
    }
    if (BNS >= 0) {
        for (int c = threadIdx.x; c < IN; c += blockDim.x) {
            float sm, sq;
            stat_read(BNS, c, sm, sq);
            float m = sm * invM;
            float v = sq * invM - m * m;
            float s = rsqrtf(v + 1e-5f) * gam[c];
            scs[c] = s;
            shs[c] = bet[c] - m * s;
        }
    }
    if (STATS >= 0 || BNS >= 0) __syncthreads();

    for (int idx = threadIdx.x; idx < OUTP * IN; idx += blockDim.x) {
        int c = idx / IN, k = idx % IN;
        Ws[k][c] = (c < OUT) ? W[c * IN + k] : 0.f;
    }
    int r0 = blockIdx.x * ROWS;
    for (int idx = threadIdx.x; idx < ROWS * IN; idx += blockDim.x) {
        int r = idx / IN, k = idx % IN;
        int gr = r0 + r;
        float xv = (gr < M) ? X[gr * IN + k] : 0.f;
        if (BNS >= 0) {
            xv = scs[k] * xv + shs[k];
            if (BRELU) xv = fmaxf(xv, 0.f);
        }
        xs[k][r] = xv;
    }
    __syncthreads();

    int tid = threadIdx.x;
    if (tid < NT) {
        int cg = tid % CG;
        int rg = tid / CG;

        float acc[4][4];
        #pragma unroll
        for (int i = 0; i < 4; i++)
            #pragma unroll
            for (int jj = 0; jj < 4; jj++) acc[i][jj] = 0.f;

        #pragma unroll 2
        for (int k = 0; k < IN; k++) {
            float4 xv = *(const float4*)&xs[k][rg * 4];
            float4 wv = *(const float4*)&Ws[k][cg * 4];
            acc[0][0] += xv.x * wv.x; acc[0][1] += xv.x * wv.y;
            acc[0][2] += xv.x * wv.z; acc[0][3] += xv.x * wv.w;
            acc[1][0] += xv.y * wv.x; acc[1][1] += xv.y * wv.y;
            acc[1][2] += xv.y * wv.z; acc[1][3] += xv.y * wv.w;
            acc[2][0] += xv.z * wv.x; acc[2][1] += xv.z * wv.y;
            acc[2][2] += xv.z * wv.z; acc[2][3] += xv.z * wv.w;
            acc[3][0] += xv.w * wv.x; acc[3][1] += xv.w * wv.y;
            acc[3][2] += xv.w * wv.z; acc[3][3] += xv.w * wv.w;
        }

        float b4[4];
        #pragma unroll
        for (int jj = 0; jj < 4; jj++) {
            int c = cg * 4 + jj;
            b4[jj] = (c < OUT) ? ((bs1 ? bs1[c] : 0.f) + (bs2 ? bs2[c] : 0.f)) : 0.f;
        }
        float ps[4] = {0.f, 0.f, 0.f, 0.f}, pq[4] = {0.f, 0.f, 0.f, 0.f};
        #pragma unroll
        for (int i = 0; i < 4; i++) {
            int gr = r0 + rg * 4 + i;
            if (gr < M) {
                #pragma unroll
                for (int jj = 0; jj < 4; jj++) {
                    int c = cg * 4 + jj;
                    if (c < OUT) {
                        float y = acc[i][jj] + b4[jj];
                        out[gr * OUT + c] = y;
                        if (STATS >= 0) { ps[jj] += y; pq[jj] += y * y; }
                    }
                }
            }
        }
        if (STATS >= 0) {
            #pragma unroll
            for (int jj = 0; jj < 4; jj++) {
                atomicAdd(&ssum[cg * 4 + jj], ps[jj]);
                atomicAdd(&ssq [cg * 4 + jj], pq[jj]);
            }
        }
    }
    if (STATS >= 0) {
        __syncthreads();
        int rb = blockIdx.x & (R_REP - 1);
        for (int c = threadIdx.x; c < OUT; c += blockDim.x) {
            atomicAdd(&g_sum[STATS][rb][c], ssum[c]);
            atomicAdd(&g_sq [STATS][rb][c], ssq[c]);
        }
    }
}

// ---------------- chunk-parallel RNN -------------------------------------------
__global__ void k_rnn_par(const float* __restrict__ Whh, int n) {
    __shared__ __align__(16) float hping[2][52];
    int j = threadIdx.x;
    float w[52];
    #pragma unroll
    for (int k = 0; k < 52; k++) w[k] = 0.f;
    if (j < 50) {
        #pragma unroll
        for (int k = 0; k < 50; k++) w[k] = Whh[j * 50 + k];
    }
    if (j < 52) { hping[0][j] = 0.f; hping[1][j] = 0.f; }
    __syncthreads();

    int start = blockIdx.x * CH_S;
    int stop  = min(start + CH_S, n);
    int t0    = max(0, start - CH_W);

    float p = (j < 50) ? g_pre[t0 * 50 + j] : 0.f;
    int ph = 0;
    for (int t = t0; t < stop; t++) {
        float pn = (j < 50) ? __ldg(&g_pre[(t + 1) * 50 + j]) : 0.f;  // pad row
        const float4* __restrict__ hv = (const float4*)hping[ph];
        float a0 = p, a1 = 0.f, a2 = 0.f, a3 = 0.f;
        float a4 = 0.f, a5 = 0.f, a6 = 0.f, a7 = 0.f;
        #pragma unroll
        for (int q = 0; q < 13; q += 2) {
            float4 hA = hv[q];
            a0 += w[4 * q + 0] * hA.x;
            a1 += w[4 * q + 1] * hA.y;
            a2 += w[4 * q + 2] * hA.z;
            a3 += w[4 * q + 3] * hA.w;
            if (q + 1 < 13) {
                float4 hB = hv[q + 1];
                a4 += w[4 * q + 4] * hB.x;
                a5 += w[4 * q + 5] * hB.y;
                a6 += w[4 * q + 6] * hB.z;
                a7 += w[4 * q + 7] * hB.w;
            }
        }
        float z = ((a0 + a1) + (a2 + a3)) + ((a4 + a5) + (a6 + a7));
        float ez = __expf(z + z);                    // tanh via exp, ~1e-7 err
        float nh = 1.f - __fdividef(2.f, ez + 1.f);
        if (j < 50) {
            hping[ph ^ 1][j] = nh;
            if (t >= start) g_ys[t * 50 + j] = nh;
        }
        __syncthreads();
        ph ^= 1;
        p = pn;
    }
}

// ---------------- fused BN4+ReLU + linear(30->30) + log_softmax ----------------
__global__ void k_final(const float* __restrict__ W, const float* __restrict__ b,
                        const float* __restrict__ gam, const float* __restrict__ bet,
                        float* __restrict__ out, int M, float invM) {
    __shared__ float sc[32], sh[32];
    if (threadIdx.x < 30) {
        int c = threadIdx.x;
        float sm, sq;
        stat_read(3, c, sm, sq);
        float m = sm * invM;
        float v = sq * invM - m * m;
        float s = rsqrtf(v + 1e-5f) * gam[c];
        sc[c] = s;
        sh[c] = bet[c] - m * s;
    }
    __syncthreads();
    int gwarp = (blockIdx.x * blockDim.x + threadIdx.x) >> 5;
    int lane = threadIdx.x & 31;
    if (gwarp >= M) return;
    const float* a = &g_z2[gwarp * 30];
    float val = 0.f;
    float mx = -1e30f;
    if (lane < 30) {
        val = b[lane];
        #pragma unroll
        for (int k = 0; k < 30; k++) {
            float av = fmaxf(sc[k] * a[k] + sh[k], 0.f);
            val += av * W[lane * 30 + k];
        }
        mx = val;
    }
    #pragma unroll
    for (int o = 16; o; o >>= 1) mx = fmaxf(mx, __shfl_xor_sync(0xffffffffu, mx, o));
    float ex = (lane < 30) ? __expf(val - mx) : 0.f;
    float sm = ex;
    #pragma unroll
    for (int o = 16; o; o >>= 1) sm += __shfl_xor_sync(0xffffffffu, sm, o);
    if (lane < 30) out[gwarp * 30 + lane] = val - mx - logf(sm);
}

// ---------------- driver --------------------------------------------------------
extern "C" void kernel_launch(void* const* d_in, const int* in_sizes, int n_in,
                              void* d_out, int out_size) {
    const float* x    = (const float*)d_in[0];
    const int*   edge = (const int*)d_in[1];        // int32 (JAX x64 disabled)
    const float *W1 = (const float*)d_in[2],  *b1  = (const float*)d_in[3];
    const float *W2 = (const float*)d_in[4],  *b2  = (const float*)d_in[5];
    const float *g1 = (const float*)d_in[6],  *be1 = (const float*)d_in[7];
    const float *g2 = (const float*)d_in[8],  *be2 = (const float*)d_in[9];
    const float *g3 = (const float*)d_in[10], *be3 = (const float*)d_in[11];
    const float *g4 = (const float*)d_in[12], *be4 = (const float*)d_in[13];
    const float *Wih = (const float*)d_in[14], *Whh = (const float*)d_in[15];
    const float *bih = (const float*)d_in[16], *bhh = (const float*)d_in[17];
    const float *lw1 = (const float*)d_in[18], *lb1 = (const float*)d_in[19];
    const float *lw2 = (const float*)d_in[20], *lb2 = (const float*)d_in[21];
    const float *lw3 = (const float*)d_in[22], *lb3 = (const float*)d_in[23];
    float* out = (float*)d_out;

    const int n = in_sizes[0] / 100;           // 50000
    const int e = in_sizes[1] / 2;             // 800000
    const float invM = 1.0f / (float)n;

    const int T = 256;
    const int nb = (n + 255) / 256;

    // lazy one-time stream/event creation
    static cudaStream_t s2 = nullptr;
    static cudaEvent_t evF = nullptr, evJ = nullptr;
    if (!s2) {
        cudaStreamCreateWithFlags(&s2, cudaStreamNonBlocking);
        cudaEventCreateWithFlags(&evF, cudaEventDisableTiming);
        cudaEventCreateWithFlags(&evJ, cudaEventDisableTiming);
    }

    const int gConv = (n + 19) / 20;
    const int gGath = (n * 32 + T - 1) / T;
    const int gMT   = (n + 31) / 32;

    // ---- fork: CSR build on s2, conv1 GEMM on main (independent) ----
    cudaEventRecord(evF, 0);
    cudaStreamWaitEvent(s2, evF, 0);

    k_zero<<<nb, T, 0, s2>>>(n);
    k_hist<<<(e + T - 1) / T, T, 0, s2>>>(edge, e);
    k_rowptr<<<nb, T, 0, s2>>>(n);
    k_fill<<<(e + T - 1) / T, T, 0, s2>>>(edge, e);
    cudaEventRecord(evJ, s2);

    k_gemm_conv<XS_EXT, -1, false><<<gConv, 128>>>(x, W1, nullptr, nullptr, n, invM);

    // ---- join: gather needs both CSR and bufA ----
    cudaStreamWaitEvent(0, evJ, 0);

    // ---- GCN conv 1 aggregation (fused BN1 stats) ----
    k_gather<0><<<gGath, T>>>(b1, n);

    // ---- GCN conv 2 (BN1+ReLU on load), aggregation (fused BN2 stats) ----
    k_gemm_conv<XS_BUFB, 0, true><<<gConv, 128>>>(nullptr, W2, g1, be1, n, invM);
    k_gather<1><<<gGath, T>>>(b2, n);

    // ---- RNN pre-activations (BN2 on load), chunk-parallel RNN ----
    k_gemm_mt<100, 50, XS_BUFB, OS_PRE, 1, false, -1>
        <<<gMT, 128>>>(nullptr, Wih, bih, bhh, g2, be2, n, invM);
    const int nchunks = (n + CH_S - 1) / CH_S;
    k_rnn_par<<<nchunks, 64>>>(Whh, n);

    // ---- Linear1 (fused BN3 output stats) ----
    k_gemm_mt<50, 50, XS_YS, OS_Z1, -1, false, 2>
        <<<gMT, 128>>>(nullptr, lw1, lb1, nullptr, nullptr, nullptr, n, invM);

    // ---- Linear2 (BN3+ReLU on load; fused BN4 output stats) ----
    k_gemm_mt<50, 30, XS_Z1, OS_Z2, 2, true, 3>
        <<<gMT, 128>>>(nullptr, lw2, lb2, nullptr, g3, be3, n, invM);

    // ---- BN4+ReLU + Linear3 + log_softmax (fused) ----
    k_final<<<(n * 32 + T - 1) / T, T>>>(lw3, lb3, g4, be4, out, n, invM);
}

// round 17
// speedup vs baseline: 1.0526x; 1.0526x over previous
#include <cuda_runtime.h>
#include <cuda_bf16.h>
#include <math.h>

#define N_MAX 50000
#define E_MAX 800000

// RNN chunking: CH_S-step chunk after CH_W-step warm-up from h=0.
#define CH_S 64
#define CH_W 40

// ---------------- PDL helpers --------------------------------------------------
// Kernels launched WITHOUT the PDL attribute see this as a no-op.
__device__ __forceinline__ void pdl_wait() {
#if defined(__CUDA_ARCH__) && __CUDA_ARCH__ >= 900
    cudaGridDependencySynchronize();
#endif
}

// ---------------- scratch (device globals; referenced directly in kernels) ----
__device__ float g_bufA[N_MAX * 100];          // xw (no bias) for gather
__device__ float g_bufB[N_MAX * 100];          // aggregated output
__device__ float g_dinv[N_MAX];
__device__ int   g_degi[N_MAX];                // incoming-edge histogram
__device__ int   g_rowptr[N_MAX];              // CSR: reserved base, then bumped to end
__device__ int   g_total;                      // reservation counter
__device__ int   g_colidx[E_MAX];              // CSR: src of each incoming edge
__device__ float g_pre [(N_MAX + 1) * 50];     // RNN pre-activations (+pad row)
__device__ float g_ys  [N_MAX * 50];
__device__ float g_z1  [N_MAX * 50];
__device__ float g_z2  [N_MAX * 30];
__device__ float g_sum [4][128];               // raw column sums per BN slot
__device__ float g_sq  [4][128];               // raw column sum-of-squares

// buffer selectors (compile-time, resolved in device code)
#define XS_EXT  0
#define XS_BUFB 1
#define XS_YS   2
#define XS_Z1   3
#define OS_PRE  1
#define OS_Z1   2
#define OS_Z2   3

template<int SEL>
__device__ __forceinline__ const float* xbuf(const float* ext) {
    if (SEL == XS_BUFB) return g_bufB;
    if (SEL == XS_YS)   return g_ys;
    if (SEL == XS_Z1)   return g_z1;
    return ext;
}
template<int SEL>
__device__ __forceinline__ float* obuf() {
    if (SEL == OS_PRE)  return g_pre;
    if (SEL == OS_Z1)   return g_z1;
    return g_z2;
}
template<int SEL>
__device__ __forceinline__ const float* bnbuf() {  // 0/1=bufB, 2=z1, 3=z2
    if (SEL <= 1) return g_bufB;
    if (SEL == 2) return g_z1;
    return g_z2;
}

// ---------------- CSR build -----------------------------------------------------
__global__ void k_zero(int n) {
    int i = blockIdx.x * blockDim.x + threadIdx.x;
    if (i < n) g_degi[i] = 0;
    if (blockIdx.x == 0 && threadIdx.x == 0) g_total = 0;
    if (blockIdx.x == 0 && threadIdx.x < 128) {
        #pragma unroll
        for (int b = 0; b < 4; b++) { g_sum[b][threadIdx.x] = 0.f; g_sq[b][threadIdx.x] = 0.f; }
    }
}

__global__ void k_hist(const int* __restrict__ edge, int e) {
    int i = blockIdx.x * blockDim.x + threadIdx.x;
    int d = (i < e) ? edge[e + i] : 0;       // input read: independent prologue
    pdl_wait();                               // wait for k_zero
    if (i < e) atomicAdd(&g_degi[d], 1);
}

// reserve a contiguous segment per node (order-free) + compute dinv
__global__ void k_rowptr(int n) {
    int i = blockIdx.x * blockDim.x + threadIdx.x;
    pdl_wait();                               // wait for k_hist
    if (i < n) {
        int d = g_degi[i];
        g_dinv[i] = rsqrtf((float)d + 1.0f);        // +1 self loop
        g_rowptr[i] = atomicAdd(&g_total, d);
    }
}

// bump rowptr[d] directly; after this kernel rowptr[d] = segment END
__global__ void k_fill(const int* __restrict__ edge, int e) {
    int i = blockIdx.x * blockDim.x + threadIdx.x;
    int s = 0, d = 0;
    if (i < e) { s = edge[i]; d = edge[e + i]; }   // input reads pre-sync
    pdl_wait();                               // wait for k_rowptr
    if (i < e) {
        int pos = atomicAdd(&g_rowptr[d], 1);
        g_colidx[pos] = s;
    }
}

// ---------------- gather aggregation: bufB[d] = bias + sum_in + self ------------
// warp per destination node; lanes 0..24 hold one float4 column group.
__global__ void k_gather(const float* __restrict__ bias, int n) {
    int warp = (blockIdx.x * blockDim.x + threadIdx.x) >> 5;
    int lane = threadIdx.x & 31;
    if (warp >= n) { pdl_wait(); return; }
    // CSR state (written long before the immediate predecessor) — pre-sync
    int p1 = g_rowptr[warp];            // post-fill: segment end
    int p0 = p1 - g_degi[warp];         // segment base
    float dd = g_dinv[warp];
    float4 bv = make_float4(0.f, 0.f, 0.f, 0.f);
    if (lane < 25) bv = ((const float4*)bias)[lane];
    pdl_wait();                          // wait for predecessor GEMM (bufA)

    float4 acc = make_float4(0.f, 0.f, 0.f, 0.f);
    if (lane < 25) {
        float4 v = ((const float4*)&g_bufA[warp * 100])[lane];
        float d2 = dd * dd;
        acc = make_float4(bv.x + v.x * d2, bv.y + v.y * d2,
                          bv.z + v.z * d2, bv.w + v.w * d2);
    }
    int i = p0;
    for (; i + 4 <= p1; i += 4) {                // unroll x4 for MLP
        int s0 = g_colidx[i + 0], s1 = g_colidx[i + 1];
        int s2 = g_colidx[i + 2], s3 = g_colidx[i + 3];
        float n0 = g_dinv[s0] * dd, n1 = g_dinv[s1] * dd;
        float n2 = g_dinv[s2] * dd, n3 = g_dinv[s3] * dd;
        if (lane < 25) {
            float4 v0 = ((const float4*)&g_bufA[s0 * 100])[lane];
            float4 v1 = ((const float4*)&g_bufA[s1 * 100])[lane];
            float4 v2 = ((const float4*)&g_bufA[s2 * 100])[lane];
            float4 v3 = ((const float4*)&g_bufA[s3 * 100])[lane];
            acc.x += v0.x * n0; acc.y += v0.y * n0; acc.z += v0.z * n0; acc.w += v0.w * n0;
            acc.x += v1.x * n1; acc.y += v1.y * n1; acc.z += v1.z * n1; acc.w += v1.w * n1;
            acc.x += v2.x * n2; acc.y += v2.y * n2; acc.z += v2.z * n2; acc.w += v2.w * n2;
            acc.x += v3.x * n3; acc.y += v3.y * n3; acc.z += v3.z * n3; acc.w += v3.w * n3;
        }
    }
    for (; i < p1; i++) {
        int s = g_colidx[i];
        float nm = g_dinv[s] * dd;
        if (lane < 25) {
            float4 v = ((const float4*)&g_bufA[s * 100])[lane];
            acc.x += v.x * nm; acc.y += v.y * nm; acc.z += v.z * nm; acc.w += v.w * nm;
        }
    }
    if (lane < 25) ((float4*)&g_bufB[warp * 100])[lane] = acc;
}

// ---------------- conv GEMM (IN=OUT=100): 4x4 register microtile ---------------
// 20-row tile, 125 active threads. smem k-major (stride 28).
template<int XSEL, int BNS, bool BRELU>
__global__ void k_gemm_conv(const float* __restrict__ Xext, const float* __restrict__ W,
                            const float* __restrict__ gam, const float* __restrict__ bet,
                            int M, float invM) {
    const float* __restrict__ X = xbuf<XSEL>(Xext);
    __shared__ __align__(16) float xs[100][28];
    __shared__ float scs[100], shs[100];

    pdl_wait();                          // stats + X both come from predecessors

    if (BNS >= 0) {
        for (int c = threadIdx.x; c < 100; c += blockDim.x) {
            float m = g_sum[BNS][c] * invM;
            float v = g_sq[BNS][c] * invM - m * m;
            float s = rsqrtf(v + 1e-5f) * gam[c];
            scs[c] = s;
            shs[c] = bet[c] - m * s;
        }
        __syncthreads();
    }

    int r0 = blockIdx.x * 20;
    for (int idx = threadIdx.x; idx < 20 * 100; idx += blockDim.x) {
        int r = idx / 100, k = idx % 100;
        int gr = r0 + r;
        float xv = (gr < M) ? X[gr * 100 + k] : 0.f;
        if (BNS >= 0) {
            xv = scs[k] * xv + shs[k];
            if (BRELU) xv = fmaxf(xv, 0.f);
        }
        xs[k][r] = xv;
    }
    __syncthreads();

    int tid = threadIdx.x;
    if (tid >= 125) return;
    int cg = tid % 25;
    int rg = tid / 25;
    float acc[4][4];
    #pragma unroll
    for (int i = 0; i < 4; i++)
        #pragma unroll
        for (int jj = 0; jj < 4; jj++) acc[i][jj] = 0.f;

    #pragma unroll 2
    for (int k = 0; k < 100; k++) {
        float4 xv = *(const float4*)&xs[k][rg * 4];
        float4 wv = *(const float4*)&W[k * 100 + cg * 4];
        acc[0][0] += xv.x * wv.x; acc[0][1] += xv.x * wv.y;
        acc[0][2] += xv.x * wv.z; acc[0][3] += xv.x * wv.w;
        acc[1][0] += xv.y * wv.x; acc[1][1] += xv.y * wv.y;
        acc[1][2] += xv.y * wv.z; acc[1][3] += xv.y * wv.w;
        acc[2][0] += xv.z * wv.x; acc[2][1] += xv.z * wv.y;
        acc[2][2] += xv.z * wv.z; acc[2][3] += xv.z * wv.w;
        acc[3][0] += xv.w * wv.x; acc[3][1] += xv.w * wv.y;
        acc[3][2] += xv.w * wv.z; acc[3][3] += xv.w * wv.w;
    }

    #pragma unroll
    for (int i = 0; i < 4; i++) {
        int gr = r0 + rg * 4 + i;
        if (gr < M)
            ((float4*)&g_bufA[gr * 100])[cg] =
                make_float4(acc[i][0], acc[i][1], acc[i][2], acc[i][3]);
    }
}

// ---------------- microtiled small GEMM (torch W [OUT,IN]) ---------------------
// W staged (independent) BEFORE the PDL wait — real prologue overlap.
template<int IN, int OUT, int XSEL, int OSEL, int BNS, bool BRELU>
__global__ void k_gemm_mt(const float* __restrict__ Xext, const float* __restrict__ W,
                          const float* __restrict__ bs1, const float* __restrict__ bs2,
                          const float* __restrict__ gam, const float* __restrict__ bet,
                          int M, float invM) {
    const int ROWS = 32;
    const int CG   = (OUT + 3) / 4;          // column groups
    const int OUTP = CG * 4;                 // padded cols
    const int NT   = CG * 8;                 // compute threads (8 row-groups)
    const float* __restrict__ X = xbuf<XSEL>(Xext);
    float* __restrict__ out = obuf<OSEL>();

    __shared__ __align__(16) float xs[IN][ROWS + 4];
    __shared__ __align__(16) float Ws[IN][OUTP + 4];
    __shared__ float scs[IN], shs[IN];

    // stage W transposed — input weights, independent of predecessor
    for (int idx = threadIdx.x; idx < OUTP * IN; idx += blockDim.x) {
        int c = idx / IN, k = idx % IN;
        Ws[k][c] = (c < OUT) ? W[c * IN + k] : 0.f;
    }

    pdl_wait();                          // wait for predecessor (X / stats)

    if (BNS >= 0) {
        for (int c = threadIdx.x; c < IN; c += blockDim.x) {
            float m = g_sum[BNS][c] * invM;
            float v = g_sq[BNS][c] * invM - m * m;
            float s = rsqrtf(v + 1e-5f) * gam[c];
            scs[c] = s;
            shs[c] = bet[c] - m * s;
        }
        __syncthreads();
    }

    // stage X k-major
    int r0 = blockIdx.x * ROWS;
    for (int idx = threadIdx.x; idx < ROWS * IN; idx += blockDim.x) {
        int r = idx / IN, k = idx % IN;
        int gr = r0 + r;
        float xv = (gr < M) ? X[gr * IN + k] : 0.f;
        if (BNS >= 0) {
            xv = scs[k] * xv + shs[k];
            if (BRELU) xv = fmaxf(xv, 0.f);
        }
        xs[k][r] = xv;
    }
    __syncthreads();

    int tid = threadIdx.x;
    if (tid >= NT) return;
    int cg = tid % CG;
    int rg = tid / CG;

    float acc[4][4];
    #pragma unroll
    for (int i = 0; i < 4; i++)
        #pragma unroll
        for (int jj = 0; jj < 4; jj++) acc[i][jj] = 0.f;

    #pragma unroll 2
    for (int k = 0; k < IN; k++) {
        float4 xv = *(const float4*)&xs[k][rg * 4];
        float4 wv = *(const float4*)&Ws[k][cg * 4];
        acc[0][0] += xv.x * wv.x; acc[0][1] += xv.x * wv.y;
        acc[0][2] += xv.x * wv.z; acc[0][3] += xv.x * wv.w;
        acc[1][0] += xv.y * wv.x; acc[1][1] += xv.y * wv.y;
        acc[1][2] += xv.y * wv.z; acc[1][3] += xv.y * wv.w;
        acc[2][0] += xv.z * wv.x; acc[2][1] += xv.z * wv.y;
        acc[2][2] += xv.z * wv.z; acc[2][3] += xv.z * wv.w;
        acc[3][0] += xv.w * wv.x; acc[3][1] += xv.w * wv.y;
        acc[3][2] += xv.w * wv.z; acc[3][3] += xv.w * wv.w;
    }

    float b4[4];
    #pragma unroll
    for (int jj = 0; jj < 4; jj++) {
        int c = cg * 4 + jj;
        b4[jj] = (c < OUT) ? ((bs1 ? bs1[c] : 0.f) + (bs2 ? bs2[c] : 0.f)) : 0.f;
    }
    #pragma unroll
    for (int i = 0; i < 4; i++) {
        int gr = r0 + rg * 4 + i;
        if (gr < M) {
            #pragma unroll
            for (int jj = 0; jj < 4; jj++) {
                int c = cg * 4 + jj;
                if (c < OUT) out[gr * OUT + c] = acc[i][jj] + b4[jj];
            }
        }
    }
}

// ---------------- BN column statistics (196 blocks; L2-resident reads) ---------
template<int C, int BSEL>
__global__ void k_colstats(int M, int slot) {
    const float* __restrict__ X = bnbuf<BSEL>();
    pdl_wait();
    int c = threadIdx.x;
    int r0 = blockIdx.x * 256;
    int r1 = min(r0 + 256, M);
    if (c >= C) return;
    float s = 0.f, q = 0.f;
    for (int r = r0; r < r1; r++) {
        float v = X[r * C + c];
        s += v; q += v * v;
    }
    atomicAdd(&g_sum[slot][c], s);
    atomicAdd(&g_sq [slot][c], q);
}

// ---------------- chunk-parallel RNN -------------------------------------------
__global__ void k_rnn_par(const float* __restrict__ Whh, int n) {
    __shared__ __align__(16) float hping[2][52];
    int j = threadIdx.x;
    float w[52];
    #pragma unroll
    for (int k = 0; k < 52; k++) w[k] = 0.f;
    if (j < 50) {                         // Whh load: input, pre-sync prologue
        #pragma unroll
        for (int k = 0; k < 50; k++) w[k] = Whh[j * 50 + k];
    }
    if (j < 52) { hping[0][j] = 0.f; hping[1][j] = 0.f; }
    pdl_wait();                           // wait for pre-activation GEMM
    __syncthreads();

    int start = blockIdx.x * CH_S;
    int stop  = min(start + CH_S, n);
    int t0    = max(0, start - CH_W);

    float p = (j < 50) ? g_pre[t0 * 50 + j] : 0.f;
    int ph = 0;
    for (int t = t0; t < stop; t++) {
        float pn = (j < 50) ? __ldg(&g_pre[(t + 1) * 50 + j]) : 0.f;  // pad row
        const float4* __restrict__ hv = (const float4*)hping[ph];
        float a0 = p, a1 = 0.f, a2 = 0.f, a3 = 0.f;
        float a4 = 0.f, a5 = 0.f, a6 = 0.f, a7 = 0.f;
        #pragma unroll
        for (int q = 0; q < 13; q += 2) {
            float4 hA = hv[q];
            a0 += w[4 * q + 0] * hA.x;
            a1 += w[4 * q + 1] * hA.y;
            a2 += w[4 * q + 2] * hA.z;
            a3 += w[4 * q + 3] * hA.w;
            if (q + 1 < 13) {
                float4 hB = hv[q + 1];
                a4 += w[4 * q + 4] * hB.x;
                a5 += w[4 * q + 5] * hB.y;
                a6 += w[4 * q + 6] * hB.z;
                a7 += w[4 * q + 7] * hB.w;
            }
        }
        float z = ((a0 + a1) + (a2 + a3)) + ((a4 + a5) + (a6 + a7));
        float ez = __expf(z + z);                    // tanh via exp, ~1e-7 err
        float nh = 1.f - __fdividef(2.f, ez + 1.f);
        if (j < 50) {
            hping[ph ^ 1][j] = nh;
            if (t >= start) g_ys[t * 50 + j] = nh;
        }
        __syncthreads();
        ph ^= 1;
        p = pn;
    }
}

// ---------------- fused BN4+ReLU + linear(30->30) + log_softmax ----------------
__global__ void k_final(const float* __restrict__ W, const float* __restrict__ b,
                        const float* __restrict__ gam, const float* __restrict__ bet,
                        float* __restrict__ out, int M, float invM) {
    __shared__ float sc[32], sh[32];
    pdl_wait();
    if (threadIdx.x < 30) {
        int c = threadIdx.x;
        float m = g_sum[3][c] * invM;
        float v = g_sq[3][c] * invM - m * m;
        float s = rsqrtf(v + 1e-5f) * gam[c];
        sc[c] = s;
        sh[c] = bet[c] - m * s;
    }
    __syncthreads();
    int gwarp = (blockIdx.x * blockDim.x + threadIdx.x) >> 5;
    int lane = threadIdx.x & 31;
    if (gwarp >= M) return;
    const float* a = &g_z2[gwarp * 30];
    float val = 0.f;
    float mx = -1e30f;
    if (lane < 30) {
        val = b[lane];
        #pragma unroll
        for (int k = 0; k < 30; k++) {
            float av = fmaxf(sc[k] * a[k] + sh[k], 0.f);
            val += av * W[lane * 30 + k];
        }
        mx = val;
    }
    #pragma unroll
    for (int o = 16; o; o >>= 1) mx = fmaxf(mx, __shfl_xor_sync(0xffffffffu, mx, o));
    float ex = (lane < 30) ? __expf(val - mx) : 0.f;
    float sm = ex;
    #pragma unroll
    for (int o = 16; o; o >>= 1) sm += __shfl_xor_sync(0xffffffffu, sm, o);
    if (lane < 30) out[gwarp * 30 + lane] = val - mx - logf(sm);
}

// ---------------- PDL launch helper --------------------------------------------
template<typename F, typename... Args>
static inline void pdl(F kfn, int grid, int block, cudaStream_t st, Args... args) {
    cudaLaunchConfig_t cfg = {};
    cfg.gridDim = dim3(grid, 1, 1);
    cfg.blockDim = dim3(block, 1, 1);
    cfg.dynamicSmemBytes = 0;
    cfg.stream = st;
    cudaLaunchAttribute at[1];
    at[0].id = cudaLaunchAttributeProgrammaticStreamSerialization;
    at[0].val.programmaticStreamSerializationAllowed = 1;
    cfg.attrs = at;
    cfg.numAttrs = 1;
    cudaLaunchKernelEx(&cfg, kfn, args...);
}

// ---------------- driver --------------------------------------------------------
extern "C" void kernel_launch(void* const* d_in, const int* in_sizes, int n_in,
                              void* d_out, int out_size) {
    const float* x    = (const float*)d_in[0];
    const int*   edge = (const int*)d_in[1];        // int32 (JAX x64 disabled)
    const float *W1 = (const float*)d_in[2],  *b1  = (const float*)d_in[3];
    const float *W2 = (const float*)d_in[4],  *b2  = (const float*)d_in[5];
    const float *g1 = (const float*)d_in[6],  *be1 = (const float*)d_in[7];
    const float *g2 = (const float*)d_in[8],  *be2 = (const float*)d_in[9];
    const float *g3 = (const float*)d_in[10], *be3 = (const float*)d_in[11];
    const float *g4 = (const float*)d_in[12], *be4 = (const float*)d_in[13];
    const float *Wih = (const float*)d_in[14], *Whh = (const float*)d_in[15];
    const float *bih = (const float*)d_in[16], *bhh = (const float*)d_in[17];
    const float *lw1 = (const float*)d_in[18], *lb1 = (const float*)d_in[19];
    const float *lw2 = (const float*)d_in[20], *lb2 = (const float*)d_in[21];
    const float *lw3 = (const float*)d_in[22], *lb3 = (const float*)d_in[23];
    float* out = (float*)d_out;

    const int n = in_sizes[0] / 100;           // 50000
    const int e = in_sizes[1] / 2;             // 800000
    const float invM = 1.0f / (float)n;

    const int T = 256;
    const int nb = (n + 255) / 256;

    // lazy one-time stream/event creation
    static cudaStream_t s2 = nullptr;
    static cudaEvent_t evF = nullptr, evJ = nullptr;
    if (!s2) {
        cudaStreamCreateWithFlags(&s2, cudaStreamNonBlocking);
        cudaEventCreateWithFlags(&evF, cudaEventDisableTiming);
        cudaEventCreateWithFlags(&evJ, cudaEventDisableTiming);
    }

    const int gConv = (n + 19) / 20;
    const int gGath = (n * 32 + T - 1) / T;
    const int gMT   = (n + 31) / 32;
    const int gE    = (e + T - 1) / T;

    // ---- fork: CSR build on s2 (PDL-chained), conv1 GEMM on main ----
    cudaEventRecord(evF, 0);
    cudaStreamWaitEvent(s2, evF, 0);

    k_zero<<<nb, T, 0, s2>>>(n);
    pdl(k_hist, gE, T, s2, edge, e);
    pdl(k_rowptr, nb, T, s2, n);
    pdl(k_fill, gE, T, s2, edge, e);
    cudaEventRecord(evJ, s2);

    k_gemm_conv<XS_EXT, -1, false><<<gConv, 128>>>(x, W1, nullptr, nullptr, n, invM);

    // ---- join: gather needs both CSR and bufA ----
    cudaStreamWaitEvent(0, evJ, 0);

    // ---- GCN conv 1 aggregation + BN1 stats ----
    pdl(k_gather, gGath, T, (cudaStream_t)0, b1, n);
    pdl(k_colstats<100, 0>, nb, 128, (cudaStream_t)0, n, 0);

    // ---- GCN conv 2 (BN1+ReLU on load) ----
    pdl(k_gemm_conv<XS_BUFB, 0, true>, gConv, 128, (cudaStream_t)0,
        (const float*)nullptr, W2, g1, be1, n, invM);
    pdl(k_gather, gGath, T, (cudaStream_t)0, b2, n);
    pdl(k_colstats<100, 0>, nb, 128, (cudaStream_t)0, n, 1);

    // ---- RNN pre-activations (BN2 on load), chunk-parallel RNN ----
    pdl(k_gemm_mt<100, 50, XS_BUFB, OS_PRE, 1, false>, gMT, 128, (cudaStream_t)0,
        (const float*)nullptr, Wih, bih, bhh, g2, be2, n, invM);
    const int nchunks = (n + CH_S - 1) / CH_S;
    pdl(k_rnn_par, nchunks, 64, (cudaStream_t)0, Whh, n);

    // ---- Linear1, BN3 stats ----
    pdl(k_gemm_mt<50, 50, XS_YS, OS_Z1, -1, false>, gMT, 128, (cudaStream_t)0,
        (const float*)nullptr, lw1, lb1, (const float*)nullptr,
        (const float*)nullptr, (const float*)nullptr, n, invM);
    pdl(k_colstats<50, 2>, nb, 64, (cudaStream_t)0, n, 2);

    // ---- Linear2 (BN3+ReLU on load), BN4 stats ----
    pdl(k_gemm_mt<50, 30, XS_Z1, OS_Z2, 2, true>, gMT, 128, (cudaStream_t)0,
        (const float*)nullptr, lw2, lb2, (const float*)nullptr, g3, be3, n, invM);
    pdl(k_colstats<30, 3>, nb, 32, (cudaStream_t)0, n, 3);

    // ---- BN4+ReLU + Linear3 + log_softmax (fused) ----
    pdl(k_final, (n * 32 + T - 1) / T, T, (cudaStream_t)0,
        lw3, lb3, g4, be4, out, n, invM);
}